// round 14
// baseline (speedup 1.0000x reference)
#include <cuda_runtime.h>

// MxCorrelation: out[b, (p+4)*9+(q+4), y, x] = (1/128) * sum_c a[b,c,y,x] * b[b,c,y+p,x+q]
// p,q in [-4,4], b zero-padded. in (8,128,128,128) f32, out (8,81,128,128) f32.
//
// R14: fully-async mainloop. R12 (warp-private, barrier-free) + A ALSO moves
// through cp.async (the last synchronous global load in the mainloop was av's
// LDG.128, ~250cyc L2 latency exposed at every chunk start on all phase-locked
// warps simultaneously). Now warps only ever wait on wait_group (1 chunk of
// slack) and 29-cyc LDS chains.
//  - per lane per chunk: 12 B-cp.async + 4 A-cp.async, all warp-uniform
//  - av via LDS.128 from warp-private sA
//  - __syncwarp after wait: cross-lane cp.async visibility (windows span lanes)

#define TY    4
#define CC    4
#define ROWF  136                    // 4 halo | 128 interior | 4 pad
#define NTHR  128
#define NCH   32
#define PERBUF_B (CC * 3 * ROWF)     // 1632 floats per B buffer per warp
#define A_OFF    (2 * PERBUF_B)      // 3264: A region starts here (floats)
#define PERBUF_A (CC * 128)          // 512 floats per A buffer per warp
#define WARPF    (A_OFF + 2 * PERBUF_A)   // 4288 floats per warp
#define SMEMB    (4 * WARPF * 4)     // 68608 bytes per block

extern __shared__ float sW[];

__device__ __forceinline__ void fill_B(unsigned sf, const float* gb,
                                       bool v0, bool v1, bool v2) {
#pragma unroll
    for (int c = 0; c < CC; c++) {
        if (v0) asm volatile("cp.async.cg.shared.global [%0], [%1], 16;\n"
                             :: "r"(sf + c * (3 * ROWF * 4)), "l"(gb + c * 16384));
        if (v1) asm volatile("cp.async.cg.shared.global [%0], [%1], 16;\n"
                             :: "r"(sf + c * (3 * ROWF * 4) + ROWF * 4), "l"(gb + c * 16384 + 128));
        if (v2) asm volatile("cp.async.cg.shared.global [%0], [%1], 16;\n"
                             :: "r"(sf + c * (3 * ROWF * 4) + 2 * ROWF * 4), "l"(gb + c * 16384 + 256));
    }
}

__device__ __forceinline__ void fill_A(unsigned sfa, const float* ga) {
#pragma unroll
    for (int c = 0; c < CC; c++)
        asm volatile("cp.async.cg.shared.global [%0], [%1], 16;\n"
                     :: "r"(sfa + c * 512), "l"(ga + c * 16384));
}

__global__ __launch_bounds__(NTHR, 3)
void corr_kernel(const float* __restrict__ A, const float* __restrict__ Bm,
                 float* __restrict__ O) {
    const int t    = threadIdx.x;
    const int lane = t & 31;
    const int wid  = t >> 5;
    const int x0   = lane << 2;

    const int y0 = blockIdx.x * TY;
    const int p0 = (int)blockIdx.y * 3 - 4;
    const int bb = blockIdx.z;

    const float* Ab = A  + (size_t)bb * 2097152;
    const float* Bb = Bm + (size_t)bb * 2097152;

    float* wbase = sW + wid * WARPF;

    // zero this warp's B region once (halo + invalid rows stay 0)
    float4* z4 = (float4*)wbase;
#pragma unroll
    for (int i = 0; i < (A_OFF / 4 + 31) / 32; i++) {
        int idx = lane + i * 32;
        if (idx < A_OFF / 4) z4[idx] = make_float4(0.f, 0.f, 0.f, 0.f);
    }
    asm volatile("fence.proxy.async.shared::cta;" ::: "memory");

    // warp-uniform validity; per-lane fill addresses
    const int gy0 = y0 + p0 + wid;
    const bool v0 = (unsigned)(gy0)     < 128u;
    const bool v1 = (unsigned)(gy0 + 1) < 128u;
    const bool v2 = (unsigned)(gy0 + 2) < 128u;

    const float* gb = Bb + gy0 * 128 + lane * 4;
    const float* ga = Ab + (y0 + wid) * 128 + lane * 4;
    const unsigned sbase = (unsigned)__cvta_generic_to_shared(wbase);
    const unsigned sfB = sbase + 16 + lane * 16;                 // skip 4-float halo
    const unsigned sfA = sbase + A_OFF * 4 + lane * 16;

    // prologue: chunk 0 -> buffer 0
    fill_B(sfB, gb, v0, v1, v2);
    fill_A(sfA, ga);
    gb += CC * 16384;  ga += CC * 16384;
    asm volatile("cp.async.commit_group;\n" ::: "memory");

    float acc[3][9][4];
#pragma unroll
    for (int pp = 0; pp < 3; pp++)
#pragma unroll
        for (int q = 0; q < 9; q++)
#pragma unroll
            for (int j = 0; j < 4; j++) acc[pp][q][j] = 0.0f;

    for (int chunk = 0; chunk < NCH; chunk++) {
        const int buf  = chunk & 1;
        const int nbuf = buf ^ 1;

        asm volatile("cp.async.wait_group 0;\n" ::: "memory");
        __syncwarp();   // publish cross-lane cp.async data (windows span lanes)

        // next fill into consumed buffer (fire-and-forget, full chunk of slack)
        if (chunk + 1 < NCH) {
            fill_B(sfB + nbuf * (PERBUF_B * 4), gb, v0, v1, v2);
            fill_A(sfA + nbuf * (PERBUF_A * 4), ga);
            gb += CC * 16384;  ga += CC * 16384;
        }
        asm volatile("cp.async.commit_group;\n" ::: "memory");

        // compute: 4c x (1 LDS.128 av + 3pp x (3 LDS.128 + 36 FFMA))
        const float* baseB = wbase + buf * PERBUF_B;
        const float* baseA = wbase + A_OFF + buf * PERBUF_A;
#pragma unroll
        for (int c = 0; c < CC; c++) {
            const float4 av = *(const float4*)&baseA[c * 128 + x0];
#pragma unroll
            for (int pp = 0; pp < 3; pp++) {
                const float* row = baseB + c * (3 * ROWF) + pp * ROWF;
                float w[12];
                *(float4*)&w[0] = *(const float4*)&row[x0];
                *(float4*)&w[4] = *(const float4*)&row[x0 + 4];
                *(float4*)&w[8] = *(const float4*)&row[x0 + 8];
#pragma unroll
                for (int q = 0; q < 9; q++) {
                    acc[pp][q][0] += av.x * w[q];
                    acc[pp][q][1] += av.y * w[q + 1];
                    acc[pp][q][2] += av.z * w[q + 2];
                    acc[pp][q][3] += av.w * w[q + 3];
                }
            }
        }
    }

    // epilogue: scale, float4 coalesced stores
    const float scale = 1.0f / 128.0f;
    float* Ob = O + (size_t)bb * 81 * 16384;
#pragma unroll
    for (int pp = 0; pp < 3; pp++) {
        int dbase = (p0 + pp + 4) * 9;
#pragma unroll
        for (int q = 0; q < 9; q++) {
            float4 v;
            v.x = acc[pp][q][0] * scale;
            v.y = acc[pp][q][1] * scale;
            v.z = acc[pp][q][2] * scale;
            v.w = acc[pp][q][3] * scale;
            *(float4*)&Ob[(size_t)(dbase + q) * 16384 + (y0 + wid) * 128 + x0] = v;
        }
    }
}

extern "C" void kernel_launch(void* const* d_in, const int* in_sizes, int n_in,
                              void* d_out, int out_size) {
    const float* A = (const float*)d_in[0];
    const float* B = (const float*)d_in[1];
    float*       O = (float*)d_out;

    cudaFuncSetAttribute(corr_kernel, cudaFuncAttributeMaxDynamicSharedMemorySize, SMEMB);
    dim3 grid(32, 3, 8);
    corr_kernel<<<grid, NTHR, SMEMB>>>(A, B, O);
}